// round 5
// baseline (speedup 1.0000x reference)
#include <cuda_runtime.h>
#include <cstdint>

// Space-to-depth k=2: in [32, 224, 224, 64] f32 -> out [32, 112, 112, 256]
// out[b, ho, wo, kh*128 + kw*64 + c] = in[b, 2*ho+kh, 2*wo+kw, c]
//
// Chunk view (float4 units, C4=16 float4s per pixel):
//   input row-pair (b, 2ho & 2ho+1)  = 2*224*16 = 7168 float4s, contiguous
//   output row     (b, ho)           = 112*64   = 7168 float4s, contiguous
//   and both start at the SAME offset: chunk*7168, chunk = b*112+ho.
// Within a chunk, for output-local offset o (0..7167):
//   wo=o>>6, kh=(o>>5)&1, kw=(o>>4)&1, ci4=o&15
//   in_off = kh*3584 + (2wo+kw)*16 + ci4
//          = ((o>>5)&1)*3584 + (o>>6)*32 + (o&31)
// Pure bit math, 32-bit throughout. With item stride 256, bits 0..7 of o are
// invariant -> in_off advances by exactly 128 and out by 256 per item: the
// whole loop body is two adds + LDG.128/STG.128 with streaming hints.
// Warp-level: 32 consecutive o -> one 512B contiguous load, one 512B store.

static constexpr int THREADS = 256;
static constexpr int ITEMS   = 4;      // float4s per thread
static constexpr unsigned CHUNK_F4 = 7168;   // 2*224*16 = 112*64
// grid: x = 7 blocks per chunk (7*1024 = 7168), y = 32*112 = 3584 chunks

__global__ void __launch_bounds__(THREADS, 8)
s2d_kernel(const float4* __restrict__ in, float4* __restrict__ out)
{
    const unsigned o0   = blockIdx.x * (THREADS * ITEMS) + threadIdx.x; // 0..7167
    const unsigned base = blockIdx.y * CHUNK_F4;

    const unsigned in0  = base + ((o0 >> 5) & 1u) * 3584u
                               + (o0 >> 6) * 32u
                               + (o0 & 31u);
    const unsigned out0 = base + o0;

    float4 v[ITEMS];
#pragma unroll
    for (int j = 0; j < ITEMS; j++)
        v[j] = __ldcs(in + in0 + (unsigned)j * 128u);
#pragma unroll
    for (int j = 0; j < ITEMS; j++)
        __stcs(out + out0 + (unsigned)j * 256u, v[j]);
}

extern "C" void kernel_launch(void* const* d_in, const int* in_sizes, int n_in,
                              void* d_out, int out_size)
{
    (void)in_sizes; (void)n_in; (void)out_size;
    const float4* in  = (const float4*)d_in[0];
    float4*       out = (float4*)d_out;

    dim3 grid(7, 3584);   // 7*256*4 = 7168 float4s per chunk; 3584 chunks
    s2d_kernel<<<grid, THREADS>>>(in, out);
}

// round 7
// speedup vs baseline: 1.0034x; 1.0034x over previous
#include <cuda_runtime.h>
#include <cstdint>

// Space-to-depth k=2: in [32, 224, 224, 64] f32 -> out [32, 112, 112, 256]
// out[b, ho, wo, kh*128 + kw*64 + c] = in[b, 2*ho+kh, 2*wo+kw, c]
//
// Chunk view (float4 units, C4=16 float4s/pixel):
//   input row-pair (b, 2ho..2ho+1) and output row (b, ho) are both 7168
//   contiguous float4s starting at the SAME offset chunk*7168 (chunk=b*112+ho).
// Within a chunk, output-local offset o (0..7167) maps to input-local:
//   in_off = ((o>>5)&1)*3584 + (o>>6)*32 + (o&31)
// Warp of 32 consecutive o -> one contiguous 512B load + one 512B store.
//
// R7 (= R6 resubmit after infra failure): one CTA per chunk. THREADS=896,
// ITEMS=8 (896*8 = 7168 exactly). All 8 loads issued before any store ->
// MLP=8 per thread. Streaming cache hints (__ldcs/__stcs) keep the one-pass
// 822MB stream from churning L2.

static constexpr int THREADS = 896;          // 28 warps
static constexpr int ITEMS   = 8;
static constexpr unsigned CHUNK_F4 = 7168;   // 2*224*16 = 112*64
static constexpr unsigned CHUNKS   = 32u * 112u;   // 3584

__global__ void __launch_bounds__(THREADS)
s2d_kernel(const float4* __restrict__ in, float4* __restrict__ out)
{
    const unsigned base = blockIdx.x * CHUNK_F4;
    const unsigned tid  = threadIdx.x;

    float4 v[ITEMS];
#pragma unroll
    for (int j = 0; j < ITEMS; j++) {
        const unsigned o      = tid + (unsigned)j * THREADS;          // 0..7167
        const unsigned in_off = ((o >> 5) & 1u) * 3584u
                              + (o >> 6) * 32u
                              + (o & 31u);
        v[j] = __ldcs(in + base + in_off);
    }
#pragma unroll
    for (int j = 0; j < ITEMS; j++) {
        const unsigned o = tid + (unsigned)j * THREADS;
        __stcs(out + base + o, v[j]);
    }
}

extern "C" void kernel_launch(void* const* d_in, const int* in_sizes, int n_in,
                              void* d_out, int out_size)
{
    (void)in_sizes; (void)n_in; (void)out_size;
    const float4* in  = (const float4*)d_in[0];
    float4*       out = (float4*)d_out;

    s2d_kernel<<<CHUNKS, THREADS>>>(in, out);
}